// round 1
// baseline (speedup 1.0000x reference)
#include <cuda_runtime.h>

#define BB 16
#define TT 512
#define DD 384
#define OUT_LEN 3584            // T * (MAX_DUR - 1) = 512 * 7
#define ROWS 8                  // output rows per gather block
#define V (DD / 4)              // 96 float4 per row

// Scratch: source-row index per output row, -1 = pad. 16*3584*4 B = 229 KB (L2-resident).
__device__ int g_row_src[BB * OUT_LEN];

// Kernel A: per-batch masked cumsum + scatter of source indices.
// One block per batch, 512 threads (one per source position).
__global__ void lr_scan_scatter(const int* __restrict__ ds,
                                const int* __restrict__ ilens) {
    const int b = blockIdx.x;
    const int t = threadIdx.x;

    __shared__ int s[TT];

    const int ilen = ilens[b];
    const int d = (t < ilen) ? ds[b * TT + t] : 0;

    // Init this batch's row_src to -1 (pad). Visible to scatter after the
    // scan-loop __syncthreads barriers below.
    int* row = g_row_src + b * OUT_LEN;
    #pragma unroll
    for (int i = t; i < OUT_LEN; i += TT) row[i] = -1;

    // Hillis-Steele inclusive scan over 512 elements.
    s[t] = d;
    __syncthreads();
    #pragma unroll
    for (int off = 1; off < TT; off <<= 1) {
        int v = (t >= off) ? s[t - off] : 0;
        __syncthreads();
        s[t] += v;
        __syncthreads();
    }

    // Scatter: output rows [csum-d, csum) map to source t.
    const int end = s[t];
    for (int j = end - d; j < end; ++j) row[j] = t;
}

// Kernel B: streaming gather. One 256-thread block per ROWS output rows.
// Each block writes 8 rows * 1536 B = 12 KB contiguous, float4-vectorized.
__global__ void __launch_bounds__(256)
lr_gather(const float4* __restrict__ xs, float4* __restrict__ out) {
    const int blocks_per_batch = OUT_LEN / ROWS;     // 448
    const int blk = blockIdx.x;
    const int b = blk / blocks_per_batch;
    const int r0 = (blk - b * blocks_per_batch) * ROWS;

    __shared__ int srcs[ROWS];
    if (threadIdx.x < ROWS)
        srcs[threadIdx.x] = g_row_src[b * OUT_LEN + r0 + threadIdx.x];
    __syncthreads();

    const float4* __restrict__ xb = xs + (size_t)b * TT * V;
    float4* __restrict__ ob = out + ((size_t)b * OUT_LEN + r0) * V;

    #pragma unroll
    for (int it = 0; it < (ROWS * V) / 256; ++it) {   // 768/256 = 3 iters
        const int i = threadIdx.x + it * 256;
        const int rl = i / V;
        const int c = i - rl * V;
        const int src = srcs[rl];
        float4 val;
        if (src >= 0) {
            val = xb[src * V + c];
        } else {
            val = make_float4(0.f, 0.f, 0.f, 0.f);
        }
        ob[(size_t)rl * V + c] = val;
    }
}

extern "C" void kernel_launch(void* const* d_in, const int* in_sizes, int n_in,
                              void* d_out, int out_size) {
    const float* xs = (const float*)d_in[0];
    const int* ds = (const int*)d_in[1];
    const int* ilens = (const int*)d_in[2];
    float* out = (float*)d_out;

    lr_scan_scatter<<<BB, TT>>>(ds, ilens);
    lr_gather<<<BB * (OUT_LEN / ROWS), 256>>>((const float4*)xs, (float4*)out);
}

// round 2
// speedup vs baseline: 1.2670x; 1.2670x over previous
#include <cuda_runtime.h>
#include <cstdint>

#define BB 16
#define TT 512
#define DD 384
#define OUT_LEN 3584            // T * (MAX_DUR - 1) = 512 * 7
#define ROW_BYTES (DD * 4)      // 1536
#define ROWS 28                 // output rows per gather block (3584/28 = 128 blocks/batch)
#define BLOCKS_PER_B (OUT_LEN / ROWS)   // 128
#define GTHREADS 128

// Scratch: source-row index per output row, -1 = pad. int4-aligned.
__device__ int4 g_row_src4[BB * OUT_LEN / 4];

// ---------------------------------------------------------------------------
// Kernel A: per-batch masked cumsum (warp shfl scan) + scatter of src indices.
// One block per batch, 512 threads.
// ---------------------------------------------------------------------------
__global__ void __launch_bounds__(TT)
lr_scan_scatter(const int* __restrict__ ds, const int* __restrict__ ilens) {
    const int b = blockIdx.x;
    const int t = threadIdx.x;
    const int lane = t & 31;
    const int wid = t >> 5;            // 16 warps

    __shared__ int wsum[16];

    const int ilen = ilens[b];
    int d = (t < ilen) ? ds[b * TT + t] : 0;

    // Init this batch's row_src to -1 (int4 stores): 896 int4 per batch.
    int4* row4 = g_row_src4 + b * (OUT_LEN / 4);
    const int4 neg1 = make_int4(-1, -1, -1, -1);
    row4[t] = neg1;
    if (t < OUT_LEN / 4 - TT) row4[TT + t] = neg1;

    // Warp-level inclusive scan.
    int x = d;
    #pragma unroll
    for (int off = 1; off < 32; off <<= 1) {
        int y = __shfl_up_sync(0xFFFFFFFFu, x, off);
        if (lane >= off) x += y;
    }
    if (lane == 31) wsum[wid] = x;
    __syncthreads();

    if (wid == 0) {
        int v = (lane < 16) ? wsum[lane] : 0;
        #pragma unroll
        for (int off = 1; off < 16; off <<= 1) {
            int y = __shfl_up_sync(0xFFFFFFFFu, v, off);
            if (lane >= off) v += y;
        }
        if (lane < 16) wsum[lane] = v;
    }
    __syncthreads();

    const int end = x + ((wid > 0) ? wsum[wid - 1] : 0);

    // Scatter: output rows [end-d, end) map to source t. (Ordered after init
    // by the two __syncthreads above.)
    int* row = (int*)(g_row_src4) + b * OUT_LEN;
    for (int j = end - d; j < end; ++j) row[j] = t;
}

// ---------------------------------------------------------------------------
// Kernel B: TMA gather. One block per 28 output rows.
//   - per-row cp.async.bulk G->S loads (1536 B each) for non-pad rows
//   - cooperative zero-fill of the pad suffix
//   - one cp.async.bulk S->G store of the full 43008 B block
// ---------------------------------------------------------------------------
__global__ void __launch_bounds__(GTHREADS)
lr_gather(const float* __restrict__ xs, float* __restrict__ out) {
    __shared__ alignas(128) char buf[ROWS * ROW_BYTES];   // 43008 B
    __shared__ alignas(8) unsigned long long mbar;
    __shared__ int srcs[ROWS];
    __shared__ int p_sh;

    const int tid = threadIdx.x;
    const int b = blockIdx.x >> 7;                 // /128
    const int r0 = (blockIdx.x & 127) * ROWS;

    const int* row_src = (const int*)(g_row_src4) + b * OUT_LEN;
    if (tid < ROWS) srcs[tid] = row_src[r0 + tid];

    uint32_t mbar_s = (uint32_t)__cvta_generic_to_shared(&mbar);
    uint32_t buf_s  = (uint32_t)__cvta_generic_to_shared(buf);

    if (tid == 0) {
        asm volatile("mbarrier.init.shared::cta.b64 [%0], 1;" :: "r"(mbar_s) : "memory");
    }
    __syncthreads();

    if (tid == 0) {
        // Pads are a contiguous suffix within the block.
        int p = 0;
        while (p < ROWS && srcs[p] >= 0) ++p;
        p_sh = p;
        if (p > 0) {
            asm volatile("mbarrier.arrive.expect_tx.shared::cta.b64 _, [%0], %1;"
                         :: "r"(mbar_s), "r"((uint32_t)(p * ROW_BYTES)) : "memory");
            const char* xb = (const char*)(xs + (size_t)b * TT * DD);
            #pragma unroll 1
            for (int r = 0; r < p; ++r) {
                const char* src = xb + (size_t)srcs[r] * ROW_BYTES;
                asm volatile(
                    "cp.async.bulk.shared::cta.global.mbarrier::complete_tx::bytes "
                    "[%0], [%1], %2, [%3];"
                    :: "r"(buf_s + r * ROW_BYTES), "l"(src),
                       "r"((uint32_t)ROW_BYTES), "r"(mbar_s) : "memory");
            }
        }
    }
    __syncthreads();

    const int p = p_sh;

    // Zero-fill pad suffix (generic-proxy smem stores).
    const int nz4 = (ROWS - p) * (ROW_BYTES / 16);
    int4* z = (int4*)(buf + p * ROW_BYTES);
    for (int i = tid; i < nz4; i += GTHREADS) z[i] = make_int4(0, 0, 0, 0);

    // Wait for TMA loads (parity 0, single-use barrier).
    if (p > 0) {
        asm volatile(
            "{\n\t"
            ".reg .pred P;\n\t"
            "LR_WAIT_%=:\n\t"
            "mbarrier.try_wait.parity.shared::cta.b64 P, [%0], 0;\n\t"
            "@!P bra LR_WAIT_%=;\n\t"
            "}"
            :: "r"(mbar_s) : "memory");
    }
    __syncthreads();

    if (tid == 0) {
        // Order generic-proxy smem writes (zero fill) before async-proxy read.
        asm volatile("fence.proxy.async.shared::cta;" ::: "memory");
        char* dst = (char*)(out + ((size_t)b * OUT_LEN + r0) * DD);
        asm volatile(
            "cp.async.bulk.global.shared::cta.bulk_group [%0], [%1], %2;"
            :: "l"(dst), "r"(buf_s), "r"((uint32_t)(ROWS * ROW_BYTES)) : "memory");
        asm volatile("cp.async.bulk.commit_group;" ::: "memory");
        asm volatile("cp.async.bulk.wait_group 0;" ::: "memory");
    }
}

extern "C" void kernel_launch(void* const* d_in, const int* in_sizes, int n_in,
                              void* d_out, int out_size) {
    const float* xs = (const float*)d_in[0];
    const int* ds = (const int*)d_in[1];
    const int* ilens = (const int*)d_in[2];
    float* out = (float*)d_out;

    lr_scan_scatter<<<BB, TT>>>(ds, ilens);
    lr_gather<<<BB * BLOCKS_PER_B, GTHREADS>>>(xs, out);
}

// round 4
// speedup vs baseline: 1.5415x; 1.2166x over previous
#include <cuda_runtime.h>
#include <cstdint>

#define BB 16
#define TT 512
#define DD 384
#define OUT_LEN 3584            // T * (MAX_DUR - 1) = 512 * 7
#define ROW_BYTES (DD * 4)      // 1536
#define ROWS 16                 // output rows per block
#define BLOCKS_PER_B (OUT_LEN / ROWS)   // 224
#define NT 128                  // threads per block

// Fused kernel: per-block masked cumsum of its batch (redundant across blocks,
// ds is L2-resident) + searchsorted for this block's 16 rows + TMA gather.
__global__ void __launch_bounds__(NT)
lr_fused(const float* __restrict__ xs, const int* __restrict__ ds,
         const int* __restrict__ ilens, float* __restrict__ out) {
    __shared__ alignas(128) char buf[ROWS * ROW_BYTES];   // 24576 B
    __shared__ int csum[TT];                               // 2048 B
    __shared__ alignas(8) unsigned long long mbar;
    __shared__ int wtot[4];

    const int tid = threadIdx.x;
    const int lane = tid & 31;
    const int w = tid >> 5;                // 4 warps
    const int b = blockIdx.y;
    const int r0 = blockIdx.x * ROWS;

    uint32_t mbar_s = (uint32_t)__cvta_generic_to_shared(&mbar);
    uint32_t buf_s  = (uint32_t)__cvta_generic_to_shared(buf);

    if (tid == 0) {
        asm volatile("mbarrier.init.shared::cta.b64 [%0], 1;" :: "r"(mbar_s) : "memory");
        asm volatile("fence.proxy.async.shared::cta;" ::: "memory");
    }

    // ---- masked load: 4 consecutive durations per thread ----
    const int ilen = ilens[b];
    int4 dv = ((const int4*)(ds + b * TT))[tid];
    const int g0 = tid * 4;
    int d0 = (g0 + 0 < ilen) ? dv.x : 0;
    int d1 = (g0 + 1 < ilen) ? dv.y : 0;
    int d2 = (g0 + 2 < ilen) ? dv.z : 0;
    int d3 = (g0 + 3 < ilen) ? dv.w : 0;

    // local inclusive partials
    int p1 = d0 + d1, p2 = p1 + d2, p3 = p2 + d3;
    int tsum = p3;

    // warp inclusive scan of per-thread sums
    int x = tsum;
    #pragma unroll
    for (int off = 1; off < 32; off <<= 1) {
        int y = __shfl_up_sync(0xFFFFFFFFu, x, off);
        if (lane >= off) x += y;
    }
    if (lane == 31) wtot[w] = x;
    __syncthreads();

    int woff = 0;
    #pragma unroll
    for (int i = 0; i < 4; ++i) woff += (i < w) ? wtot[i] : 0;
    const int excl = woff + x - tsum;     // exclusive prefix for this thread

    csum[g0 + 0] = excl + d0;
    csum[g0 + 1] = excl + p1;
    csum[g0 + 2] = excl + p2;
    csum[g0 + 3] = excl + p3;
    __syncthreads();

    const int total = csum[TT - 1];
    const int p = min(max(total - r0, 0), ROWS);   // valid rows are a prefix

    // ---- searchsorted(csum, t, 'right') for this block's rows ----
    // Interval [0, 512] needs 10 halvings (lo=mid+1 asymmetry): 512->256->...->1->0.
    // Once lo==hi the extra iterations are no-ops (csum[answer] > t keeps hi=mid),
    // and answer <= T-1 for valid rows, so csum[lo] stays in-bounds.
    int src = -1;
    if (tid < p) {
        const int t = r0 + tid;
        int lo = 0, hi = TT;
        #pragma unroll
        for (int it = 0; it < 10; ++it) {
            int mid = (lo + hi) >> 1;
            if (csum[mid] <= t) lo = mid + 1; else hi = mid;
        }
        src = lo;                          // < TT guaranteed since t < total
    }

    // ---- TMA loads: lanes 0..p-1 issue one row each (warp 0 only) ----
    if (tid == 0 && p > 0) {
        asm volatile("mbarrier.arrive.expect_tx.shared::cta.b64 _, [%0], %1;"
                     :: "r"(mbar_s), "r"((uint32_t)(p * ROW_BYTES)) : "memory");
    }
    __syncwarp();
    if (tid < p) {
        const char* srcp = (const char*)(xs + (size_t)b * TT * DD) + (size_t)src * ROW_BYTES;
        asm volatile(
            "cp.async.bulk.shared::cta.global.mbarrier::complete_tx::bytes "
            "[%0], [%1], %2, [%3];"
            :: "r"(buf_s + tid * ROW_BYTES), "l"(srcp),
               "r"((uint32_t)ROW_BYTES), "r"(mbar_s) : "memory");
    }

    // ---- zero-fill pad suffix (generic-proxy smem stores) ----
    const int nz4 = (ROWS - p) * (ROW_BYTES / 16);
    int4* z = (int4*)(buf + p * ROW_BYTES);
    for (int i = tid; i < nz4; i += NT) z[i] = make_int4(0, 0, 0, 0);
    __syncthreads();

    // ---- single thread: wait loads, fence, bulk store, release smem ----
    if (tid == 0) {
        if (p > 0) {
            asm volatile(
                "{\n\t"
                ".reg .pred P;\n\t"
                "LRW_%=:\n\t"
                "mbarrier.try_wait.parity.shared::cta.b64 P, [%0], 0;\n\t"
                "@!P bra LRW_%=;\n\t"
                "}"
                :: "r"(mbar_s) : "memory");
        }
        asm volatile("fence.proxy.async.shared::cta;" ::: "memory");
        char* dst = (char*)(out + ((size_t)b * OUT_LEN + r0) * DD);
        asm volatile(
            "cp.async.bulk.global.shared::cta.bulk_group [%0], [%1], %2;"
            :: "l"(dst), "r"(buf_s), "r"((uint32_t)(ROWS * ROW_BYTES)) : "memory");
        asm volatile("cp.async.bulk.commit_group;" ::: "memory");
        // Only wait until smem has been READ; global writes drain after exit.
        asm volatile("cp.async.bulk.wait_group.read 0;" ::: "memory");
    }
}

extern "C" void kernel_launch(void* const* d_in, const int* in_sizes, int n_in,
                              void* d_out, int out_size) {
    const float* xs = (const float*)d_in[0];
    const int* ds = (const int*)d_in[1];
    const int* ilens = (const int*)d_in[2];
    float* out = (float*)d_out;

    dim3 grid(BLOCKS_PER_B, BB);
    lr_fused<<<grid, NT>>>(xs, ds, ilens, out);
}